// round 15
// baseline (speedup 1.0000x reference)
#include <cuda_runtime.h>
#include <cuda_fp16.h>
#include <cstdint>

#define N_MAX   100000
#define E_MAX   1600000
#define EL_MAX  6400000

// ---------------- scratch (device globals; fp16 chain intermediates) ----------
__device__ __half g_y16[E_MAX * 16];
__device__ __half g_ze1[E_MAX * 16];
__device__ __half g_ze2[E_MAX * 16];
__device__ __half g_zet[E_MAX * 16];
__device__ __half g_ze4[E_MAX * 16];
__device__ __half g_xyagg[E_MAX * 16];
__device__ __half g_zn1[N_MAX * 16];
__device__ __half g_zn2[N_MAX * 16];
__device__ __half g_znt[N_MAX * 16];
__device__ __half g_zn4[N_MAX * 16];
__device__ __half g_yx[N_MAX * 16];
__device__ __half g_h16[(N_MAX + E_MAX) * 16];   // pre-BN activations, fp16

__device__ int g_tmp_lg[E_MAX];        // counts, then cursors
__device__ int g_off_lg[E_MAX + 1];
__device__ int g_csr_lg[EL_MAX];
__device__ int g_tmp_g[N_MAX];
__device__ int g_off_g[N_MAX + 1];
__device__ int g_csr_g_src[E_MAX];
__device__ int g_csr_g_eid[E_MAX];
__device__ int g_bsums_lg[2048];
__device__ int g_bsums_g[256];

__device__ float g_stats[64];
__device__ float g_bn[64];

static inline unsigned cdiv_u(long long a, long long b) { return (unsigned)((a + b - 1) / b); }

// ---------------- f32x2 helpers ----------------
__device__ __forceinline__ unsigned long long pk2(float a, float b) {
    unsigned long long r;
    asm("mov.b64 %0, {%1, %2};" : "=l"(r) : "r"(__float_as_uint(a)), "r"(__float_as_uint(b)));
    return r;
}
__device__ __forceinline__ unsigned long long fma2(
    unsigned long long a, unsigned long long b, unsigned long long c) {
    unsigned long long d;
    asm("fma.rn.f32x2 %0, %1, %2, %3;" : "=l"(d) : "l"(a), "l"(b), "l"(c));
    return d;
}
__device__ __forceinline__ void up2(unsigned long long v, float& lo, float& hi) {
    unsigned int a, b;
    asm("mov.b64 {%0, %1}, %2;" : "=r"(a), "=r"(b) : "l"(v));
    lo = __uint_as_float(a); hi = __uint_as_float(b);
}

// ---------------- fp16 pack/unpack helpers ----------------
__device__ __forceinline__ uint2 f4_to_h8(float4 a) {
    uint2 o;
    __half2 lo = __floats2half2_rn(a.x, a.y);
    __half2 hi = __floats2half2_rn(a.z, a.w);
    o.x = *reinterpret_cast<unsigned*>(&lo);
    o.y = *reinterpret_cast<unsigned*>(&hi);
    return o;
}
__device__ __forceinline__ float4 h8_to_f4(uint2 raw) {
    float2 f0 = __half22float2(*reinterpret_cast<__half2*>(&raw.x));
    float2 f1 = __half22float2(*reinterpret_cast<__half2*>(&raw.y));
    return make_float4(f0.x, f0.y, f1.x, f1.y);
}
__device__ __forceinline__ void h16_to_f(uint4 ra, uint4 rb, float* v) {
    __half2* h = reinterpret_cast<__half2*>(&ra);
    #pragma unroll
    for (int i = 0; i < 4; i++) {
        float2 f = __half22float2(h[i]);
        v[2 * i] = f.x; v[2 * i + 1] = f.y;
    }
    __half2* h2 = reinterpret_cast<__half2*>(&rb);
    #pragma unroll
    for (int i = 0; i < 4; i++) {
        float2 f = __half22float2(h2[i]);
        v[8 + 2 * i] = f.x; v[8 + 2 * i + 1] = f.y;
    }
}
__device__ __forceinline__ uint4 f8_to_h8(const float* v) {
    uint4 o;
    __half2 a = __floats2half2_rn(v[0], v[1]);
    __half2 b = __floats2half2_rn(v[2], v[3]);
    __half2 c = __floats2half2_rn(v[4], v[5]);
    __half2 d = __floats2half2_rn(v[6], v[7]);
    o.x = *reinterpret_cast<unsigned*>(&a);
    o.y = *reinterpret_cast<unsigned*>(&b);
    o.z = *reinterpret_cast<unsigned*>(&c);
    o.w = *reinterpret_cast<unsigned*>(&d);
    return o;
}

// ---------------- init: zero counts/stats + y->fp16 conversion (fused) --------
__global__ void __launch_bounds__(256) init_k(
    const float* __restrict__ y, __half* __restrict__ y16, int nE, int nN)
{
    long long i = (long long)blockIdx.x * 256 + threadIdx.x;
    long long n8 = (long long)nE * 2;   // 8-elem chunks of y
    if (i < n8) {
        const float4* p = (const float4*)y + i * 2;
        float4 a = __ldcs(p), b = __ldcs(p + 1);
        uint2 ra = f4_to_h8(a), rb = f4_to_h8(b);
        ((uint4*)y16)[i] = make_uint4(ra.x, ra.y, rb.x, rb.y);
    }
    if (i < nE) g_tmp_lg[i] = 0;
    if (i < nN) g_tmp_g[i] = 0;
    if (i < 64) g_stats[i] = 0.f;
}

// ---------------- CSR build (dual-graph fused launches) ----------------
__global__ void __launch_bounds__(256) hist_dual(
    const int* __restrict__ dst_lg, const int* __restrict__ dst_g, int nEL, int nE)
{
    long long i = (long long)blockIdx.x * 256 + threadIdx.x;
    if (i < nEL) {
        atomicAdd(g_tmp_lg + __ldcs(dst_lg + i), 1);
    } else {
        long long j = i - nEL;
        if (j < nE) atomicAdd(g_tmp_g + __ldcs(dst_g + j), 1);
    }
}

__device__ __forceinline__ void scan_block_body(
    const int* cnt, int* off, int* bsums, int n, int blk)
{
    __shared__ int warpsum[8];
    int t = threadIdx.x;
    int i0 = blk * 1024 + t * 4;
    int4 v = make_int4(0, 0, 0, 0);
    if (i0 + 3 < n) v = *(const int4*)(cnt + i0);
    else {
        if (i0 < n)     v.x = cnt[i0];
        if (i0 + 1 < n) v.y = cnt[i0 + 1];
        if (i0 + 2 < n) v.z = cnt[i0 + 2];
    }
    int s = v.x + v.y + v.z + v.w;
    int lane = t & 31, w = t >> 5;
    int incl = s;
    #pragma unroll
    for (int o = 1; o < 32; o <<= 1) {
        int nv = __shfl_up_sync(0xFFFFFFFFu, incl, o);
        if (lane >= o) incl += nv;
    }
    if (lane == 31) warpsum[w] = incl;
    __syncthreads();
    if (t < 8) {
        int ws = warpsum[t];
        int in2 = ws;
        #pragma unroll
        for (int o = 1; o < 8; o <<= 1) {
            int nv = __shfl_up_sync(0x000000FFu, in2, o);
            if (t >= o) in2 += nv;
        }
        warpsum[t] = in2 - ws;  // exclusive
    }
    __syncthreads();
    int excl = warpsum[w] + incl - s;
    if (i0 < n) {
        int a = excl;
        off[i0] = a; a += v.x;
        if (i0 + 1 < n) off[i0 + 1] = a; a += v.y;
        if (i0 + 2 < n) off[i0 + 2] = a; a += v.z;
        if (i0 + 3 < n) off[i0 + 3] = a;
    }
    if (t == 255) bsums[blk] = excl + s;  // block total
}

__global__ void __launch_bounds__(256) scan_blocks_dual(int nb_lg, int nE, int nN) {
    int b = blockIdx.x;
    if (b < nb_lg) scan_block_body(g_tmp_lg, g_off_lg, g_bsums_lg, nE, b);
    else           scan_block_body(g_tmp_g,  g_off_g,  g_bsums_g,  nN, b - nb_lg);
}

__device__ __forceinline__ void scan_bsums_body(int* bsums, int nb) {
    __shared__ int wsum[32];
    int t = threadIdx.x;
    int k = (nb + 1023) >> 10;
    int i0 = t * k;
    int s = 0;
    for (int q = 0; q < k; q++) { int i = i0 + q; if (i < nb) s += bsums[i]; }
    int lane = t & 31, w = t >> 5;
    int incl = s;
    #pragma unroll
    for (int o = 1; o < 32; o <<= 1) {
        int nv = __shfl_up_sync(0xFFFFFFFFu, incl, o);
        if (lane >= o) incl += nv;
    }
    if (lane == 31) wsum[w] = incl;
    __syncthreads();
    if (t < 32) {
        int ws = wsum[t];
        int in2 = ws;
        #pragma unroll
        for (int o = 1; o < 32; o <<= 1) {
            int nv = __shfl_up_sync(0xFFFFFFFFu, in2, o);
            if (t >= o) in2 += nv;
        }
        wsum[t] = in2 - ws;
    }
    __syncthreads();
    int excl = wsum[w] + incl - s;
    for (int q = 0; q < k; q++) {
        int i = i0 + q;
        if (i < nb) { int v = bsums[i]; bsums[i] = excl; excl += v; }
    }
}

__global__ void __launch_bounds__(1024) scan_bsums_dual(int nb_lg, int nb_g) {
    if (blockIdx.x == 0) scan_bsums_body(g_bsums_lg, nb_lg);
    else                 scan_bsums_body(g_bsums_g,  nb_g);
}

__global__ void __launch_bounds__(256) add_offsets_dual(int nE, int nN, int nEL) {
    long long i = (long long)blockIdx.x * 256 + threadIdx.x;
    if (i < nE) {
        int v = g_off_lg[i] + __ldg(g_bsums_lg + (i >> 10));
        g_off_lg[i] = v;
        g_tmp_lg[i] = v;
        if (i == 0) g_off_lg[nE] = nEL;
    } else {
        long long j = i - nE;
        if (j < nN) {
            int v = g_off_g[j] + __ldg(g_bsums_g + (j >> 10));
            g_off_g[j] = v;
            g_tmp_g[j] = v;
            if (j == 0) g_off_g[nN] = nE;
        }
    }
}

__global__ void __launch_bounds__(256) scatter_dual(
    const int* __restrict__ src_lg, const int* __restrict__ dst_lg,
    const int* __restrict__ src_g, const int* __restrict__ dst_g,
    int nEL, int nE)
{
    long long i = (long long)blockIdx.x * 256 + threadIdx.x;
    if (i < nEL) {
        int p = atomicAdd(g_tmp_lg + __ldcs(dst_lg + i), 1);
        g_csr_lg[p] = __ldcs(src_lg + i);
    } else {
        long long j = i - nEL;
        if (j < nE) {
            int p = atomicAdd(g_tmp_g + __ldcs(dst_g + j), 1);
            g_csr_g_src[p] = __ldcs(src_g + j);
            g_csr_g_eid[p] = (int)j;
        }
    }
}

// ---------------- chain pass (lg + g fused): out = A z for both graphs -------
// Index traffic (off/csr) uses evict-first loads so the reused z arrays stay
// L2-resident (src 51MB + dst 51MB < 126MB once index streams stop polluting).
__global__ void __launch_bounds__(256) spmm_dual(
    const __half* __restrict__ z_lg, __half* __restrict__ out_lg, int nlg,
    const __half* __restrict__ z_g,  __half* __restrict__ out_g,  int ng)
{
    long long t = (long long)blockIdx.x * 256 + threadIdx.x;
    long long lgT = (long long)nlg * 4;
    if (t < lgT) {
        int d = (int)(t >> 2), c = (int)(t & 3);
        int k0 = __ldcs(g_off_lg + d), k1 = __ldcs(g_off_lg + d + 1);
        float4 acc = make_float4(0.f, 0.f, 0.f, 0.f);
        #pragma unroll 4
        for (int k = k0; k < k1; k++) {
            int s = __ldcs(g_csr_lg + k);
            float4 v = h8_to_f4(__ldg((const uint2*)z_lg + (size_t)s * 4 + c));
            acc.x += v.x; acc.y += v.y; acc.z += v.z; acc.w += v.w;
        }
        ((uint2*)out_lg)[(size_t)d * 4 + c] = f4_to_h8(acc);
    } else {
        long long u = t - lgT;
        if (u >= (long long)ng * 4) return;
        int d = (int)(u >> 2), c = (int)(u & 3);
        int k0 = __ldcs(g_off_g + d), k1 = __ldcs(g_off_g + d + 1);
        float4 acc = make_float4(0.f, 0.f, 0.f, 0.f);
        #pragma unroll 4
        for (int k = k0; k < k1; k++) {
            int s = __ldcs(g_csr_g_src + k);
            float4 v = h8_to_f4(__ldg((const uint2*)z_g + (size_t)s * 4 + c));
            acc.x += v.x; acc.y += v.y; acc.z += v.z; acc.w += v.w;
        }
        ((uint2*)out_g)[(size_t)d * 4 + c] = f4_to_h8(acc);
    }
}

// pass1 fused: lg: ze1 = A y16, xyagg = A x[e2n];  g: zn1 = A x, yx = sum y16[eid]
__global__ void __launch_bounds__(256) pass1_dual(
    const __half* __restrict__ y16, const float* __restrict__ x,
    const int* __restrict__ e2n,
    __half* __restrict__ ze1, __half* __restrict__ xyagg, int nlg,
    __half* __restrict__ zn1, __half* __restrict__ yx, int ng)
{
    long long t = (long long)blockIdx.x * 256 + threadIdx.x;
    long long lgT = (long long)nlg * 4;
    if (t < lgT) {
        int d = (int)(t >> 2), c = (int)(t & 3);
        int k0 = __ldcs(g_off_lg + d), k1 = __ldcs(g_off_lg + d + 1);
        float4 ay = make_float4(0.f, 0.f, 0.f, 0.f);
        float4 ax = make_float4(0.f, 0.f, 0.f, 0.f);
        #pragma unroll 4
        for (int k = k0; k < k1; k++) {
            int s = __ldcs(g_csr_lg + k);
            float4 v = h8_to_f4(__ldg((const uint2*)y16 + (size_t)s * 4 + c));
            ay.x += v.x; ay.y += v.y; ay.z += v.z; ay.w += v.w;
            int nid = __ldg(e2n + s);
            float4 w = __ldg((const float4*)x + (size_t)nid * 4 + c);
            ax.x += w.x; ax.y += w.y; ax.z += w.z; ax.w += w.w;
        }
        ((uint2*)ze1)[(size_t)d * 4 + c] = f4_to_h8(ay);
        ((uint2*)xyagg)[(size_t)d * 4 + c] = f4_to_h8(ax);
    } else {
        long long u = t - lgT;
        if (u >= (long long)ng * 4) return;
        int d = (int)(u >> 2), c = (int)(u & 3);
        int k0 = __ldcs(g_off_g + d), k1 = __ldcs(g_off_g + d + 1);
        float4 ax = make_float4(0.f, 0.f, 0.f, 0.f);
        float4 ay = make_float4(0.f, 0.f, 0.f, 0.f);
        #pragma unroll 4
        for (int k = k0; k < k1; k++) {
            int s = __ldcs(g_csr_g_src + k);
            int e = __ldcs(g_csr_g_eid + k);
            float4 v = __ldg((const float4*)x + (size_t)s * 4 + c);
            ax.x += v.x; ax.y += v.y; ax.z += v.z; ax.w += v.w;
            float4 w = h8_to_f4(__ldg((const uint2*)y16 + (size_t)e * 4 + c));
            ay.x += w.x; ay.y += w.y; ay.z += w.z; ay.w += w.w;
        }
        ((uint2*)zn1)[(size_t)d * 4 + c] = f4_to_h8(ax);
        ((uint2*)yx)[(size_t)d * 4 + c] = f4_to_h8(ay);
    }
}

// ---------------- fused 6-way lin + relu-fold + BN stats (both branches) ------
// All per-row input streams are read exactly once -> evict-first loads.
__global__ void __launch_bounds__(256) gemm_dual(
    const float* __restrict__ x, const __half* __restrict__ y16,
    const float* __restrict__ deg_g, const float* __restrict__ deg_lg,
    const __half* __restrict__ yx, const __half* __restrict__ zn1,
    const __half* __restrict__ zn2, const __half* __restrict__ zn4,
    const __half* __restrict__ xyagg, const __half* __restrict__ ze1,
    const __half* __restrict__ ze2, const __half* __restrict__ ze4,
    const float* __restrict__ theta_W, const float* __restrict__ theta_b,
    const float* __restrict__ gamma_W, const float* __restrict__ gamma_b,
    __half* __restrict__ h16, int N, int E, int gridN)
{
    __shared__ float ws[96 * 32];
    __shared__ unsigned long long bs2[16];
    __shared__ float redbuf[8 * 32];

    int statsel = (blockIdx.x < gridN) ? 0 : 1;
    int blk = statsel ? (blockIdx.x - gridN) : blockIdx.x;
    int nrows = statsel ? E : N;
    const float*  in0f = statsel ? nullptr : x;
    const __half* in0h = statsel ? y16 : nullptr;
    const float*  deg  = statsel ? deg_lg : deg_g;
    const __half* agg  = statsel ? xyagg : yx;
    const __half* z1p  = statsel ? ze1 : zn1;
    const __half* z2p  = statsel ? ze2 : zn2;
    const __half* z4p  = statsel ? ze4 : zn4;
    const float*  W    = statsel ? gamma_W : theta_W;
    const float*  Bv   = statsel ? gamma_b : theta_b;
    __half* hout = statsel ? (h16 + (size_t)N * 16) : h16;

    for (int t = threadIdx.x; t < 96 * 32; t += 256) {
        int kb = t >> 9;
        int rem = t & 511;
        int j = rem >> 4;
        int i = rem & 15;
        ws[(kb * 16 + i) * 32 + j] = W[t];
    }
    if (threadIdx.x < 16) {
        float lo = 0.f, hi = 0.f;
        #pragma unroll
        for (int kb = 0; kb < 6; kb++) {
            lo += Bv[kb * 32 + 2 * threadIdx.x];
            hi += Bv[kb * 32 + 2 * threadIdx.x + 1];
        }
        bs2[threadIdx.x] = pk2(lo, hi);
    }
    __syncthreads();

    int r0 = blk * 512 + threadIdx.x;
    int r1 = r0 + 256;
    bool ok0 = r0 < nrows, ok1 = r1 < nrows;

    unsigned long long acc0[16], acc1[16];
    #pragma unroll
    for (int q = 0; q < 16; q++) { acc0[q] = bs2[q]; acc1[q] = bs2[q]; }

    float v0[16], v1[16];
    #pragma unroll
    for (int q = 0; q < 16; q++) { v0[q] = 0.f; v1[q] = 0.f; }
    float dg0 = ok0 ? __ldg(deg + r0) : 0.f;
    float dg1 = ok1 ? __ldg(deg + r1) : 0.f;

    #pragma unroll 1
    for (int kb = 0; kb < 6; kb++) {
        if (kb <= 1) {
            if (kb == 0) {
                if (in0h) {
                    if (ok0) {
                        const uint4* hp = (const uint4*)in0h + (size_t)r0 * 2;
                        uint4 ra = __ldcs(hp), rb = __ldcs(hp + 1);
                        h16_to_f(ra, rb, v0);
                    }
                    if (ok1) {
                        const uint4* hp = (const uint4*)in0h + (size_t)r1 * 2;
                        uint4 ra = __ldcs(hp), rb = __ldcs(hp + 1);
                        h16_to_f(ra, rb, v1);
                    }
                } else {
                    if (ok0) {
                        const float4* p = (const float4*)in0f + (size_t)r0 * 4;
                        float4 a = __ldcs(p), b = __ldcs(p + 1), c = __ldcs(p + 2), d = __ldcs(p + 3);
                        v0[0]=a.x; v0[1]=a.y; v0[2]=a.z; v0[3]=a.w;
                        v0[4]=b.x; v0[5]=b.y; v0[6]=b.z; v0[7]=b.w;
                        v0[8]=c.x; v0[9]=c.y; v0[10]=c.z; v0[11]=c.w;
                        v0[12]=d.x; v0[13]=d.y; v0[14]=d.z; v0[15]=d.w;
                    }
                    if (ok1) {
                        const float4* p = (const float4*)in0f + (size_t)r1 * 4;
                        float4 a = __ldcs(p), b = __ldcs(p + 1), c = __ldcs(p + 2), d = __ldcs(p + 3);
                        v1[0]=a.x; v1[1]=a.y; v1[2]=a.z; v1[3]=a.w;
                        v1[4]=b.x; v1[5]=b.y; v1[6]=b.z; v1[7]=b.w;
                        v1[8]=c.x; v1[9]=c.y; v1[10]=c.z; v1[11]=c.w;
                        v1[12]=d.x; v1[13]=d.y; v1[14]=d.z; v1[15]=d.w;
                    }
                }
            } else {
                #pragma unroll
                for (int q = 0; q < 16; q++) { v0[q] *= dg0; v1[q] *= dg1; }
            }
        } else {
            const __half* sp = (kb == 2) ? agg : (kb == 3) ? z1p
                             : (kb == 4) ? z2p : z4p;
            if (ok0) {
                const uint4* hp = (const uint4*)sp + (size_t)r0 * 2;
                uint4 ra = __ldcs(hp), rb = __ldcs(hp + 1);
                h16_to_f(ra, rb, v0);
            }
            if (ok1) {
                const uint4* hp = (const uint4*)sp + (size_t)r1 * 2;
                uint4 ra = __ldcs(hp), rb = __ldcs(hp + 1);
                h16_to_f(ra, rb, v1);
            }
        }
        #pragma unroll
        for (int i = 0; i < 16; i++) {
            unsigned long long vd0 = pk2(v0[i], v0[i]);
            unsigned long long vd1 = pk2(v1[i], v1[i]);
            const ulonglong2* wp2 = (const ulonglong2*)&ws[(kb * 16 + i) * 32];
            #pragma unroll
            for (int q2 = 0; q2 < 8; q2++) {
                ulonglong2 ww = wp2[q2];
                acc0[2*q2]   = fma2(vd0, ww.x, acc0[2*q2]);
                acc0[2*q2+1] = fma2(vd0, ww.y, acc0[2*q2+1]);
                acc1[2*q2]   = fma2(vd1, ww.x, acc1[2*q2]);
                acc1[2*q2+1] = fma2(vd1, ww.y, acc1[2*q2+1]);
            }
        }
    }

    float hs[16], hq[16];
    #pragma unroll
    for (int c = 0; c < 16; c++) { hs[c] = 0.f; hq[c] = 0.f; }

    if (ok0) {
        float h[16];
        #pragma unroll
        for (int q = 0; q < 8; q++) {
            float a0, a1, b0, b1;
            up2(acc0[q], a0, a1);
            up2(acc0[8 + q], b0, b1);
            h[2*q]   = a0 + fmaxf(b0, 0.f);
            h[2*q+1] = a1 + fmaxf(b1, 0.f);
        }
        uint4* ho = (uint4*)hout + (size_t)r0 * 2;
        ho[0] = f8_to_h8(h);
        ho[1] = f8_to_h8(h + 8);
        #pragma unroll
        for (int c = 0; c < 16; c++) { hs[c] += h[c]; hq[c] += h[c] * h[c]; }
    }
    if (ok1) {
        float h[16];
        #pragma unroll
        for (int q = 0; q < 8; q++) {
            float a0, a1, b0, b1;
            up2(acc1[q], a0, a1);
            up2(acc1[8 + q], b0, b1);
            h[2*q]   = a0 + fmaxf(b0, 0.f);
            h[2*q+1] = a1 + fmaxf(b1, 0.f);
        }
        uint4* ho = (uint4*)hout + (size_t)r1 * 2;
        ho[0] = f8_to_h8(h);
        ho[1] = f8_to_h8(h + 8);
        #pragma unroll
        for (int c = 0; c < 16; c++) { hs[c] += h[c]; hq[c] += h[c] * h[c]; }
    }

    int lane = threadIdx.x & 31;
    int warp = threadIdx.x >> 5;
    #pragma unroll
    for (int c = 0; c < 16; c++) {
        float a = hs[c];
        float b = hq[c];
        #pragma unroll
        for (int o = 16; o > 0; o >>= 1) {
            a += __shfl_xor_sync(0xFFFFFFFFu, a, o);
            b += __shfl_xor_sync(0xFFFFFFFFu, b, o);
        }
        if (lane == 0) {
            redbuf[warp * 32 + c]      = a;
            redbuf[warp * 32 + 16 + c] = b;
        }
    }
    __syncthreads();
    if (threadIdx.x < 32) {
        float s = 0.f;
        #pragma unroll
        for (int w = 0; w < 8; w++) s += redbuf[w * 32 + threadIdx.x];
        atomicAdd(&g_stats[statsel * 32 + threadIdx.x], s);
    }
}

// ---------------- BN finalize + apply (reads fp16 h, writes fp32 output) -------
__global__ void bn_finalize(
    const float* __restrict__ wx, const float* __restrict__ bx,
    const float* __restrict__ wy, const float* __restrict__ by,
    int N, int E)
{
    int t = threadIdx.x;
    if (t >= 32) return;
    int sel = t >> 4;
    int c = t & 15;
    float cnt = sel ? (float)E : (float)N;
    float m   = g_stats[sel * 32 + c] / cnt;
    float var = g_stats[sel * 32 + 16 + c] / cnt - m * m;
    const float* w = sel ? wy : wx;
    const float* b = sel ? by : bx;
    float scale = rsqrtf(var + 1e-5f) * __ldg(w + c);
    g_bn[sel * 32 + c]      = scale;
    g_bn[sel * 32 + 16 + c] = __ldg(b + c) - m * scale;
}

__global__ void __launch_bounds__(256) bn_apply_all(
    const __half* __restrict__ h16, float* __restrict__ outp, int N, int E)
{
    long long i = (long long)blockIdx.x * blockDim.x + threadIdx.x;  // quarter-row index
    long long nx = (long long)N * 4;
    long long tot = nx + (long long)E * 4;
    if (i >= tot) return;
    int bnoff = (i < nx) ? 0 : 32;
    int c = ((int)(i & 3)) * 4;
    const float* bn = g_bn + bnoff;
    float4 v = h8_to_f4(__ldcs((const uint2*)h16 + i));
    v.x = v.x * bn[c + 0] + bn[16 + c + 0];
    v.y = v.y * bn[c + 1] + bn[16 + c + 1];
    v.z = v.z * bn[c + 2] + bn[16 + c + 2];
    v.w = v.w * bn[c + 3] + bn[16 + c + 3];
    __stcs((float4*)outp + i, v);
}

// ---------------- host ----------------
static void* sym_addr(const void* s) {
    void* p = nullptr;
    cudaGetSymbolAddress(&p, s);
    return p;
}

extern "C" void kernel_launch(void* const* d_in, const int* in_sizes, int n_in,
                              void* d_out, int out_size)
{
    const float* x       = (const float*)d_in[0];
    const float* y       = (const float*)d_in[1];
    const float* deg_g   = (const float*)d_in[2];
    const float* deg_lg  = (const float*)d_in[3];
    const float* theta_W = (const float*)d_in[4];
    const float* theta_b = (const float*)d_in[5];
    const float* gamma_W = (const float*)d_in[6];
    const float* gamma_b = (const float*)d_in[7];
    const float* bn_x_w  = (const float*)d_in[8];
    const float* bn_x_b  = (const float*)d_in[9];
    const float* bn_y_w  = (const float*)d_in[10];
    const float* bn_y_b  = (const float*)d_in[11];
    const int* src_g     = (const int*)d_in[12];
    const int* dst_g     = (const int*)d_in[13];
    const int* src_lg    = (const int*)d_in[14];
    const int* dst_lg    = (const int*)d_in[15];
    const int* eid2nid   = (const int*)d_in[16];

    int N  = in_sizes[0] / 16;
    int E  = in_sizes[1] / 16;
    int EL = in_sizes[14];

    float* out_all = (float*)d_out;

    __half* y16   = (__half*)sym_addr(g_y16);
    __half* ze1   = (__half*)sym_addr(g_ze1);
    __half* ze2   = (__half*)sym_addr(g_ze2);
    __half* zet   = (__half*)sym_addr(g_zet);
    __half* ze4   = (__half*)sym_addr(g_ze4);
    __half* xyagg = (__half*)sym_addr(g_xyagg);
    __half* zn1   = (__half*)sym_addr(g_zn1);
    __half* zn2   = (__half*)sym_addr(g_zn2);
    __half* znt   = (__half*)sym_addr(g_znt);
    __half* zn4   = (__half*)sym_addr(g_zn4);
    __half* yx    = (__half*)sym_addr(g_yx);
    __half* h16   = (__half*)sym_addr(g_h16);

    // 1) fused init: zero counts/stats + y->fp16
    init_k<<<cdiv_u((long long)E * 2, 256), 256>>>(y, y16, E, N);

    // 2) CSR build for both graphs (fused dual launches)
    hist_dual<<<cdiv_u((long long)EL + E, 256), 256>>>(dst_lg, dst_g, EL, E);

    int nb_lg = cdiv_u(E, 1024);
    int nb_g  = cdiv_u(N, 1024);
    scan_blocks_dual<<<nb_lg + nb_g, 256>>>(nb_lg, E, N);
    scan_bsums_dual<<<2, 1024>>>(nb_lg, nb_g);
    add_offsets_dual<<<cdiv_u((long long)E + N, 256), 256>>>(E, N, EL);
    scatter_dual<<<cdiv_u((long long)EL + E, 256), 256>>>(src_lg, dst_lg, src_g, dst_g, EL, E);

    // 3) fused chains: pass k runs lg + g concurrently in one launch
    unsigned gall = cdiv_u((long long)(E + N) * 4, 256);
    pass1_dual<<<gall, 256>>>(y16, x, eid2nid, ze1, xyagg, E, zn1, yx, N);
    spmm_dual<<<gall, 256>>>(ze1, ze2, E, zn1, zn2, N);
    spmm_dual<<<gall, 256>>>(ze2, zet, E, zn2, znt, N);
    spmm_dual<<<gall, 256>>>(zet, ze4, E, znt, zn4, N);

    // 4) fused GEMM (node + edge in one launch) -> fp16 h
    int gridN = cdiv_u(N, 512);
    int gridE = cdiv_u(E, 512);
    gemm_dual<<<gridN + gridE, 256>>>(x, y16, deg_g, deg_lg,
                                      yx, zn1, zn2, zn4,
                                      xyagg, ze1, ze2, ze4,
                                      theta_W, theta_b, gamma_W, gamma_b,
                                      h16, N, E, gridN);

    // 5) BN finalize + apply (fp16 h in -> fp32 d_out)
    bn_finalize<<<1, 32>>>(bn_x_w, bn_x_b, bn_y_w, bn_y_b, N, E);
    bn_apply_all<<<cdiv_u((long long)(N + E) * 4, 256), 256>>>(h16, out_all, N, E);

    (void)n_in; (void)out_size;
}

// round 16
// speedup vs baseline: 1.0496x; 1.0496x over previous
#include <cuda_runtime.h>
#include <cuda_fp16.h>
#include <cstdint>

#define N_MAX   100000
#define E_MAX   1600000
#define EL_MAX  6400000

// ---------------- scratch (device globals; fp16 chain intermediates) ----------
__device__ __half g_y16[E_MAX * 16];
__device__ __half g_ze1[E_MAX * 16];
__device__ __half g_ze2[E_MAX * 16];
__device__ __half g_zet[E_MAX * 16];
__device__ __half g_ze4[E_MAX * 16];
__device__ __half g_xyagg[E_MAX * 16];
__device__ __half g_zn1[N_MAX * 16];
__device__ __half g_zn2[N_MAX * 16];
__device__ __half g_znt[N_MAX * 16];
__device__ __half g_zn4[N_MAX * 16];
__device__ __half g_yx[N_MAX * 16];
__device__ __half g_h16[(N_MAX + E_MAX) * 16];   // pre-BN activations, fp16

__device__ int g_tmp_lg[E_MAX];        // counts, then cursors
__device__ int g_off_lg[E_MAX + 1];
__device__ int g_csr_lg[EL_MAX];
__device__ int g_tmp_g[N_MAX];
__device__ int g_off_g[N_MAX + 1];
__device__ int g_csr_g_src[E_MAX];
__device__ int g_csr_g_eid[E_MAX];
__device__ int g_bsums_lg[2048];
__device__ int g_bsums_g[256];

__device__ float g_stats[64];
__device__ float g_bn[64];

static inline unsigned cdiv_u(long long a, long long b) { return (unsigned)((a + b - 1) / b); }

// ---------------- f32x2 helpers ----------------
__device__ __forceinline__ unsigned long long pk2(float a, float b) {
    unsigned long long r;
    asm("mov.b64 %0, {%1, %2};" : "=l"(r) : "r"(__float_as_uint(a)), "r"(__float_as_uint(b)));
    return r;
}
__device__ __forceinline__ unsigned long long fma2(
    unsigned long long a, unsigned long long b, unsigned long long c) {
    unsigned long long d;
    asm("fma.rn.f32x2 %0, %1, %2, %3;" : "=l"(d) : "l"(a), "l"(b), "l"(c));
    return d;
}
__device__ __forceinline__ void up2(unsigned long long v, float& lo, float& hi) {
    unsigned int a, b;
    asm("mov.b64 {%0, %1}, %2;" : "=r"(a), "=r"(b) : "l"(v));
    lo = __uint_as_float(a); hi = __uint_as_float(b);
}

// ---------------- fp16 pack/unpack helpers ----------------
__device__ __forceinline__ uint2 f4_to_h8(float4 a) {
    uint2 o;
    __half2 lo = __floats2half2_rn(a.x, a.y);
    __half2 hi = __floats2half2_rn(a.z, a.w);
    o.x = *reinterpret_cast<unsigned*>(&lo);
    o.y = *reinterpret_cast<unsigned*>(&hi);
    return o;
}
__device__ __forceinline__ float4 h8_to_f4(uint2 raw) {
    float2 f0 = __half22float2(*reinterpret_cast<__half2*>(&raw.x));
    float2 f1 = __half22float2(*reinterpret_cast<__half2*>(&raw.y));
    return make_float4(f0.x, f0.y, f1.x, f1.y);
}
__device__ __forceinline__ void h16_to_f(uint4 ra, uint4 rb, float* v) {
    __half2* h = reinterpret_cast<__half2*>(&ra);
    #pragma unroll
    for (int i = 0; i < 4; i++) {
        float2 f = __half22float2(h[i]);
        v[2 * i] = f.x; v[2 * i + 1] = f.y;
    }
    __half2* h2 = reinterpret_cast<__half2*>(&rb);
    #pragma unroll
    for (int i = 0; i < 4; i++) {
        float2 f = __half22float2(h2[i]);
        v[8 + 2 * i] = f.x; v[8 + 2 * i + 1] = f.y;
    }
}
__device__ __forceinline__ uint4 f8_to_h8(const float* v) {
    uint4 o;
    __half2 a = __floats2half2_rn(v[0], v[1]);
    __half2 b = __floats2half2_rn(v[2], v[3]);
    __half2 c = __floats2half2_rn(v[4], v[5]);
    __half2 d = __floats2half2_rn(v[6], v[7]);
    o.x = *reinterpret_cast<unsigned*>(&a);
    o.y = *reinterpret_cast<unsigned*>(&b);
    o.z = *reinterpret_cast<unsigned*>(&c);
    o.w = *reinterpret_cast<unsigned*>(&d);
    return o;
}

// ---------------- init: zero counts/stats + y->fp16 conversion (fused) --------
__global__ void __launch_bounds__(256) init_k(
    const float* __restrict__ y, __half* __restrict__ y16, int nE, int nN)
{
    long long i = (long long)blockIdx.x * 256 + threadIdx.x;
    long long n8 = (long long)nE * 2;   // 8-elem chunks of y
    if (i < n8) {
        const float4* p = (const float4*)y + i * 2;
        float4 a = __ldg(p), b = __ldg(p + 1);
        uint2 ra = f4_to_h8(a), rb = f4_to_h8(b);
        ((uint4*)y16)[i] = make_uint4(ra.x, ra.y, rb.x, rb.y);
    }
    if (i < nE) g_tmp_lg[i] = 0;
    if (i < nN) g_tmp_g[i] = 0;
    if (i < 64) g_stats[i] = 0.f;
}

// ---------------- CSR build (dual-graph fused launches) ----------------
__global__ void __launch_bounds__(256) hist_dual(
    const int* __restrict__ dst_lg, const int* __restrict__ dst_g, int nEL, int nE)
{
    long long i = (long long)blockIdx.x * 256 + threadIdx.x;
    if (i < nEL) {
        atomicAdd(g_tmp_lg + __ldg(dst_lg + i), 1);
    } else {
        long long j = i - nEL;
        if (j < nE) atomicAdd(g_tmp_g + __ldg(dst_g + j), 1);
    }
}

__device__ __forceinline__ void scan_block_body(
    const int* cnt, int* off, int* bsums, int n, int blk)
{
    __shared__ int warpsum[8];
    int t = threadIdx.x;
    int i0 = blk * 1024 + t * 4;
    int4 v = make_int4(0, 0, 0, 0);
    if (i0 + 3 < n) v = *(const int4*)(cnt + i0);
    else {
        if (i0 < n)     v.x = cnt[i0];
        if (i0 + 1 < n) v.y = cnt[i0 + 1];
        if (i0 + 2 < n) v.z = cnt[i0 + 2];
    }
    int s = v.x + v.y + v.z + v.w;
    int lane = t & 31, w = t >> 5;
    int incl = s;
    #pragma unroll
    for (int o = 1; o < 32; o <<= 1) {
        int nv = __shfl_up_sync(0xFFFFFFFFu, incl, o);
        if (lane >= o) incl += nv;
    }
    if (lane == 31) warpsum[w] = incl;
    __syncthreads();
    if (t < 8) {
        int ws = warpsum[t];
        int in2 = ws;
        #pragma unroll
        for (int o = 1; o < 8; o <<= 1) {
            int nv = __shfl_up_sync(0x000000FFu, in2, o);
            if (t >= o) in2 += nv;
        }
        warpsum[t] = in2 - ws;  // exclusive
    }
    __syncthreads();
    int excl = warpsum[w] + incl - s;
    if (i0 < n) {
        int a = excl;
        off[i0] = a; a += v.x;
        if (i0 + 1 < n) off[i0 + 1] = a; a += v.y;
        if (i0 + 2 < n) off[i0 + 2] = a; a += v.z;
        if (i0 + 3 < n) off[i0 + 3] = a;
    }
    if (t == 255) bsums[blk] = excl + s;  // block total
}

__global__ void __launch_bounds__(256) scan_blocks_dual(int nb_lg, int nE, int nN) {
    int b = blockIdx.x;
    if (b < nb_lg) scan_block_body(g_tmp_lg, g_off_lg, g_bsums_lg, nE, b);
    else           scan_block_body(g_tmp_g,  g_off_g,  g_bsums_g,  nN, b - nb_lg);
}

__device__ __forceinline__ void scan_bsums_body(int* bsums, int nb) {
    __shared__ int wsum[32];
    int t = threadIdx.x;
    int k = (nb + 1023) >> 10;
    int i0 = t * k;
    int s = 0;
    for (int q = 0; q < k; q++) { int i = i0 + q; if (i < nb) s += bsums[i]; }
    int lane = t & 31, w = t >> 5;
    int incl = s;
    #pragma unroll
    for (int o = 1; o < 32; o <<= 1) {
        int nv = __shfl_up_sync(0xFFFFFFFFu, incl, o);
        if (lane >= o) incl += nv;
    }
    if (lane == 31) wsum[w] = incl;
    __syncthreads();
    if (t < 32) {
        int ws = wsum[t];
        int in2 = ws;
        #pragma unroll
        for (int o = 1; o < 32; o <<= 1) {
            int nv = __shfl_up_sync(0xFFFFFFFFu, in2, o);
            if (t >= o) in2 += nv;
        }
        wsum[t] = in2 - ws;
    }
    __syncthreads();
    int excl = wsum[w] + incl - s;
    for (int q = 0; q < k; q++) {
        int i = i0 + q;
        if (i < nb) { int v = bsums[i]; bsums[i] = excl; excl += v; }
    }
}

__global__ void __launch_bounds__(1024) scan_bsums_dual(int nb_lg, int nb_g) {
    if (blockIdx.x == 0) scan_bsums_body(g_bsums_lg, nb_lg);
    else                 scan_bsums_body(g_bsums_g,  nb_g);
}

__global__ void __launch_bounds__(256) add_offsets_dual(int nE, int nN, int nEL) {
    long long i = (long long)blockIdx.x * 256 + threadIdx.x;
    if (i < nE) {
        int v = g_off_lg[i] + __ldg(g_bsums_lg + (i >> 10));
        g_off_lg[i] = v;
        g_tmp_lg[i] = v;
        if (i == 0) g_off_lg[nE] = nEL;
    } else {
        long long j = i - nE;
        if (j < nN) {
            int v = g_off_g[j] + __ldg(g_bsums_g + (j >> 10));
            g_off_g[j] = v;
            g_tmp_g[j] = v;
            if (j == 0) g_off_g[nN] = nE;
        }
    }
}

__global__ void __launch_bounds__(256) scatter_dual(
    const int* __restrict__ src_lg, const int* __restrict__ dst_lg,
    const int* __restrict__ src_g, const int* __restrict__ dst_g,
    int nEL, int nE)
{
    long long i = (long long)blockIdx.x * 256 + threadIdx.x;
    if (i < nEL) {
        int p = atomicAdd(g_tmp_lg + __ldg(dst_lg + i), 1);
        g_csr_lg[p] = __ldg(src_lg + i);
    } else {
        long long j = i - nEL;
        if (j < nE) {
            int p = atomicAdd(g_tmp_g + __ldg(dst_g + j), 1);
            g_csr_g_src[p] = __ldg(src_g + j);
            g_csr_g_eid[p] = (int)j;
        }
    }
}

// ---------------- chain pass (lg + g fused): out = A z for both graphs -------
__global__ void __launch_bounds__(256) spmm_dual(
    const __half* __restrict__ z_lg, __half* __restrict__ out_lg, int nlg,
    const __half* __restrict__ z_g,  __half* __restrict__ out_g,  int ng)
{
    long long t = (long long)blockIdx.x * 256 + threadIdx.x;
    long long lgT = (long long)nlg * 4;
    if (t < lgT) {
        int d = (int)(t >> 2), c = (int)(t & 3);
        int k0 = __ldg(g_off_lg + d), k1 = __ldg(g_off_lg + d + 1);
        float4 acc = make_float4(0.f, 0.f, 0.f, 0.f);
        #pragma unroll 4
        for (int k = k0; k < k1; k++) {
            int s = __ldg(g_csr_lg + k);
            float4 v = h8_to_f4(__ldg((const uint2*)z_lg + (size_t)s * 4 + c));
            acc.x += v.x; acc.y += v.y; acc.z += v.z; acc.w += v.w;
        }
        ((uint2*)out_lg)[(size_t)d * 4 + c] = f4_to_h8(acc);
    } else {
        long long u = t - lgT;
        if (u >= (long long)ng * 4) return;
        int d = (int)(u >> 2), c = (int)(u & 3);
        int k0 = __ldg(g_off_g + d), k1 = __ldg(g_off_g + d + 1);
        float4 acc = make_float4(0.f, 0.f, 0.f, 0.f);
        #pragma unroll 4
        for (int k = k0; k < k1; k++) {
            int s = __ldg(g_csr_g_src + k);
            float4 v = h8_to_f4(__ldg((const uint2*)z_g + (size_t)s * 4 + c));
            acc.x += v.x; acc.y += v.y; acc.z += v.z; acc.w += v.w;
        }
        ((uint2*)out_g)[(size_t)d * 4 + c] = f4_to_h8(acc);
    }
}

// pass1 fused: lg: ze1 = A y16, xyagg = A x[e2n];  g: zn1 = A x, yx = sum y16[eid]
__global__ void __launch_bounds__(256) pass1_dual(
    const __half* __restrict__ y16, const float* __restrict__ x,
    const int* __restrict__ e2n,
    __half* __restrict__ ze1, __half* __restrict__ xyagg, int nlg,
    __half* __restrict__ zn1, __half* __restrict__ yx, int ng)
{
    long long t = (long long)blockIdx.x * 256 + threadIdx.x;
    long long lgT = (long long)nlg * 4;
    if (t < lgT) {
        int d = (int)(t >> 2), c = (int)(t & 3);
        int k0 = __ldg(g_off_lg + d), k1 = __ldg(g_off_lg + d + 1);
        float4 ay = make_float4(0.f, 0.f, 0.f, 0.f);
        float4 ax = make_float4(0.f, 0.f, 0.f, 0.f);
        #pragma unroll 4
        for (int k = k0; k < k1; k++) {
            int s = __ldg(g_csr_lg + k);
            float4 v = h8_to_f4(__ldg((const uint2*)y16 + (size_t)s * 4 + c));
            ay.x += v.x; ay.y += v.y; ay.z += v.z; ay.w += v.w;
            int nid = __ldg(e2n + s);
            float4 w = __ldg((const float4*)x + (size_t)nid * 4 + c);
            ax.x += w.x; ax.y += w.y; ax.z += w.z; ax.w += w.w;
        }
        ((uint2*)ze1)[(size_t)d * 4 + c] = f4_to_h8(ay);
        ((uint2*)xyagg)[(size_t)d * 4 + c] = f4_to_h8(ax);
    } else {
        long long u = t - lgT;
        if (u >= (long long)ng * 4) return;
        int d = (int)(u >> 2), c = (int)(u & 3);
        int k0 = __ldg(g_off_g + d), k1 = __ldg(g_off_g + d + 1);
        float4 ax = make_float4(0.f, 0.f, 0.f, 0.f);
        float4 ay = make_float4(0.f, 0.f, 0.f, 0.f);
        #pragma unroll 4
        for (int k = k0; k < k1; k++) {
            int s = __ldg(g_csr_g_src + k);
            int e = __ldg(g_csr_g_eid + k);
            float4 v = __ldg((const float4*)x + (size_t)s * 4 + c);
            ax.x += v.x; ax.y += v.y; ax.z += v.z; ax.w += v.w;
            float4 w = h8_to_f4(__ldg((const uint2*)y16 + (size_t)e * 4 + c));
            ay.x += w.x; ay.y += w.y; ay.z += w.z; ay.w += w.w;
        }
        ((uint2*)zn1)[(size_t)d * 4 + c] = f4_to_h8(ax);
        ((uint2*)yx)[(size_t)d * 4 + c] = f4_to_h8(ay);
    }
}

// ---------------- fused 6-way lin + relu-fold + BN stats (both branches) ------
__global__ void __launch_bounds__(256) gemm_dual(
    const float* __restrict__ x, const __half* __restrict__ y16,
    const float* __restrict__ deg_g, const float* __restrict__ deg_lg,
    const __half* __restrict__ yx, const __half* __restrict__ zn1,
    const __half* __restrict__ zn2, const __half* __restrict__ zn4,
    const __half* __restrict__ xyagg, const __half* __restrict__ ze1,
    const __half* __restrict__ ze2, const __half* __restrict__ ze4,
    const float* __restrict__ theta_W, const float* __restrict__ theta_b,
    const float* __restrict__ gamma_W, const float* __restrict__ gamma_b,
    __half* __restrict__ h16, int N, int E, int gridN)
{
    __shared__ float ws[96 * 32];
    __shared__ unsigned long long bs2[16];
    __shared__ float redbuf[8 * 32];

    int statsel = (blockIdx.x < gridN) ? 0 : 1;
    int blk = statsel ? (blockIdx.x - gridN) : blockIdx.x;
    int nrows = statsel ? E : N;
    const float*  in0f = statsel ? nullptr : x;
    const __half* in0h = statsel ? y16 : nullptr;
    const float*  deg  = statsel ? deg_lg : deg_g;
    const __half* agg  = statsel ? xyagg : yx;
    const __half* z1p  = statsel ? ze1 : zn1;
    const __half* z2p  = statsel ? ze2 : zn2;
    const __half* z4p  = statsel ? ze4 : zn4;
    const float*  W    = statsel ? gamma_W : theta_W;
    const float*  Bv   = statsel ? gamma_b : theta_b;
    __half* hout = statsel ? (h16 + (size_t)N * 16) : h16;

    for (int t = threadIdx.x; t < 96 * 32; t += 256) {
        int kb = t >> 9;
        int rem = t & 511;
        int j = rem >> 4;
        int i = rem & 15;
        ws[(kb * 16 + i) * 32 + j] = W[t];
    }
    if (threadIdx.x < 16) {
        float lo = 0.f, hi = 0.f;
        #pragma unroll
        for (int kb = 0; kb < 6; kb++) {
            lo += Bv[kb * 32 + 2 * threadIdx.x];
            hi += Bv[kb * 32 + 2 * threadIdx.x + 1];
        }
        bs2[threadIdx.x] = pk2(lo, hi);
    }
    __syncthreads();

    int r0 = blk * 512 + threadIdx.x;
    int r1 = r0 + 256;
    bool ok0 = r0 < nrows, ok1 = r1 < nrows;

    unsigned long long acc0[16], acc1[16];
    #pragma unroll
    for (int q = 0; q < 16; q++) { acc0[q] = bs2[q]; acc1[q] = bs2[q]; }

    float v0[16], v1[16];
    #pragma unroll
    for (int q = 0; q < 16; q++) { v0[q] = 0.f; v1[q] = 0.f; }
    float dg0 = ok0 ? __ldg(deg + r0) : 0.f;
    float dg1 = ok1 ? __ldg(deg + r1) : 0.f;

    #pragma unroll 1
    for (int kb = 0; kb < 6; kb++) {
        if (kb <= 1) {
            if (kb == 0) {
                if (in0h) {
                    if (ok0) {
                        const uint4* hp = (const uint4*)in0h + (size_t)r0 * 2;
                        uint4 ra = __ldg(hp), rb = __ldg(hp + 1);
                        h16_to_f(ra, rb, v0);
                    }
                    if (ok1) {
                        const uint4* hp = (const uint4*)in0h + (size_t)r1 * 2;
                        uint4 ra = __ldg(hp), rb = __ldg(hp + 1);
                        h16_to_f(ra, rb, v1);
                    }
                } else {
                    if (ok0) {
                        const float4* p = (const float4*)in0f + (size_t)r0 * 4;
                        float4 a = __ldg(p), b = __ldg(p + 1), c = __ldg(p + 2), d = __ldg(p + 3);
                        v0[0]=a.x; v0[1]=a.y; v0[2]=a.z; v0[3]=a.w;
                        v0[4]=b.x; v0[5]=b.y; v0[6]=b.z; v0[7]=b.w;
                        v0[8]=c.x; v0[9]=c.y; v0[10]=c.z; v0[11]=c.w;
                        v0[12]=d.x; v0[13]=d.y; v0[14]=d.z; v0[15]=d.w;
                    }
                    if (ok1) {
                        const float4* p = (const float4*)in0f + (size_t)r1 * 4;
                        float4 a = __ldg(p), b = __ldg(p + 1), c = __ldg(p + 2), d = __ldg(p + 3);
                        v1[0]=a.x; v1[1]=a.y; v1[2]=a.z; v1[3]=a.w;
                        v1[4]=b.x; v1[5]=b.y; v1[6]=b.z; v1[7]=b.w;
                        v1[8]=c.x; v1[9]=c.y; v1[10]=c.z; v1[11]=c.w;
                        v1[12]=d.x; v1[13]=d.y; v1[14]=d.z; v1[15]=d.w;
                    }
                }
            } else {
                #pragma unroll
                for (int q = 0; q < 16; q++) { v0[q] *= dg0; v1[q] *= dg1; }
            }
        } else {
            const __half* sp = (kb == 2) ? agg : (kb == 3) ? z1p
                             : (kb == 4) ? z2p : z4p;
            if (ok0) {
                const uint4* hp = (const uint4*)sp + (size_t)r0 * 2;
                uint4 ra = __ldg(hp), rb = __ldg(hp + 1);
                h16_to_f(ra, rb, v0);
            }
            if (ok1) {
                const uint4* hp = (const uint4*)sp + (size_t)r1 * 2;
                uint4 ra = __ldg(hp), rb = __ldg(hp + 1);
                h16_to_f(ra, rb, v1);
            }
        }
        #pragma unroll
        for (int i = 0; i < 16; i++) {
            unsigned long long vd0 = pk2(v0[i], v0[i]);
            unsigned long long vd1 = pk2(v1[i], v1[i]);
            const ulonglong2* wp2 = (const ulonglong2*)&ws[(kb * 16 + i) * 32];
            #pragma unroll
            for (int q2 = 0; q2 < 8; q2++) {
                ulonglong2 ww = wp2[q2];
                acc0[2*q2]   = fma2(vd0, ww.x, acc0[2*q2]);
                acc0[2*q2+1] = fma2(vd0, ww.y, acc0[2*q2+1]);
                acc1[2*q2]   = fma2(vd1, ww.x, acc1[2*q2]);
                acc1[2*q2+1] = fma2(vd1, ww.y, acc1[2*q2+1]);
            }
        }
    }

    float hs[16], hq[16];
    #pragma unroll
    for (int c = 0; c < 16; c++) { hs[c] = 0.f; hq[c] = 0.f; }

    if (ok0) {
        float h[16];
        #pragma unroll
        for (int q = 0; q < 8; q++) {
            float a0, a1, b0, b1;
            up2(acc0[q], a0, a1);
            up2(acc0[8 + q], b0, b1);
            h[2*q]   = a0 + fmaxf(b0, 0.f);
            h[2*q+1] = a1 + fmaxf(b1, 0.f);
        }
        uint4* ho = (uint4*)hout + (size_t)r0 * 2;
        ho[0] = f8_to_h8(h);
        ho[1] = f8_to_h8(h + 8);
        #pragma unroll
        for (int c = 0; c < 16; c++) { hs[c] += h[c]; hq[c] += h[c] * h[c]; }
    }
    if (ok1) {
        float h[16];
        #pragma unroll
        for (int q = 0; q < 8; q++) {
            float a0, a1, b0, b1;
            up2(acc1[q], a0, a1);
            up2(acc1[8 + q], b0, b1);
            h[2*q]   = a0 + fmaxf(b0, 0.f);
            h[2*q+1] = a1 + fmaxf(b1, 0.f);
        }
        uint4* ho = (uint4*)hout + (size_t)r1 * 2;
        ho[0] = f8_to_h8(h);
        ho[1] = f8_to_h8(h + 8);
        #pragma unroll
        for (int c = 0; c < 16; c++) { hs[c] += h[c]; hq[c] += h[c] * h[c]; }
    }

    int lane = threadIdx.x & 31;
    int warp = threadIdx.x >> 5;
    #pragma unroll
    for (int c = 0; c < 16; c++) {
        float a = hs[c];
        float b = hq[c];
        #pragma unroll
        for (int o = 16; o > 0; o >>= 1) {
            a += __shfl_xor_sync(0xFFFFFFFFu, a, o);
            b += __shfl_xor_sync(0xFFFFFFFFu, b, o);
        }
        if (lane == 0) {
            redbuf[warp * 32 + c]      = a;
            redbuf[warp * 32 + 16 + c] = b;
        }
    }
    __syncthreads();
    if (threadIdx.x < 32) {
        float s = 0.f;
        #pragma unroll
        for (int w = 0; w < 8; w++) s += redbuf[w * 32 + threadIdx.x];
        atomicAdd(&g_stats[statsel * 32 + threadIdx.x], s);
    }
}

// ---------------- BN finalize + apply (reads fp16 h, writes fp32 output) -------
__global__ void bn_finalize(
    const float* __restrict__ wx, const float* __restrict__ bx,
    const float* __restrict__ wy, const float* __restrict__ by,
    int N, int E)
{
    int t = threadIdx.x;
    if (t >= 32) return;
    int sel = t >> 4;
    int c = t & 15;
    float cnt = sel ? (float)E : (float)N;
    float m   = g_stats[sel * 32 + c] / cnt;
    float var = g_stats[sel * 32 + 16 + c] / cnt - m * m;
    const float* w = sel ? wy : wx;
    const float* b = sel ? by : bx;
    float scale = rsqrtf(var + 1e-5f) * __ldg(w + c);
    g_bn[sel * 32 + c]      = scale;
    g_bn[sel * 32 + 16 + c] = __ldg(b + c) - m * scale;
}

__global__ void __launch_bounds__(256) bn_apply_all(
    const __half* __restrict__ h16, float* __restrict__ outp, int N, int E)
{
    long long i = (long long)blockIdx.x * blockDim.x + threadIdx.x;  // quarter-row index
    long long nx = (long long)N * 4;
    long long tot = nx + (long long)E * 4;
    if (i >= tot) return;
    int bnoff = (i < nx) ? 0 : 32;
    int c = ((int)(i & 3)) * 4;
    const float* bn = g_bn + bnoff;
    float4 v = h8_to_f4(__ldg((const uint2*)h16 + i));
    v.x = v.x * bn[c + 0] + bn[16 + c + 0];
    v.y = v.y * bn[c + 1] + bn[16 + c + 1];
    v.z = v.z * bn[c + 2] + bn[16 + c + 2];
    v.w = v.w * bn[c + 3] + bn[16 + c + 3];
    __stcs((float4*)outp + i, v);   // output never re-read: streaming store
}

// ---------------- host ----------------
static void* sym_addr(const void* s) {
    void* p = nullptr;
    cudaGetSymbolAddress(&p, s);
    return p;
}

extern "C" void kernel_launch(void* const* d_in, const int* in_sizes, int n_in,
                              void* d_out, int out_size)
{
    const float* x       = (const float*)d_in[0];
    const float* y       = (const float*)d_in[1];
    const float* deg_g   = (const float*)d_in[2];
    const float* deg_lg  = (const float*)d_in[3];
    const float* theta_W = (const float*)d_in[4];
    const float* theta_b = (const float*)d_in[5];
    const float* gamma_W = (const float*)d_in[6];
    const float* gamma_b = (const float*)d_in[7];
    const float* bn_x_w  = (const float*)d_in[8];
    const float* bn_x_b  = (const float*)d_in[9];
    const float* bn_y_w  = (const float*)d_in[10];
    const float* bn_y_b  = (const float*)d_in[11];
    const int* src_g     = (const int*)d_in[12];
    const int* dst_g     = (const int*)d_in[13];
    const int* src_lg    = (const int*)d_in[14];
    const int* dst_lg    = (const int*)d_in[15];
    const int* eid2nid   = (const int*)d_in[16];

    int N  = in_sizes[0] / 16;
    int E  = in_sizes[1] / 16;
    int EL = in_sizes[14];

    float* out_all = (float*)d_out;

    __half* y16   = (__half*)sym_addr(g_y16);
    __half* ze1   = (__half*)sym_addr(g_ze1);
    __half* ze2   = (__half*)sym_addr(g_ze2);
    __half* zet   = (__half*)sym_addr(g_zet);
    __half* ze4   = (__half*)sym_addr(g_ze4);
    __half* xyagg = (__half*)sym_addr(g_xyagg);
    __half* zn1   = (__half*)sym_addr(g_zn1);
    __half* zn2   = (__half*)sym_addr(g_zn2);
    __half* znt   = (__half*)sym_addr(g_znt);
    __half* zn4   = (__half*)sym_addr(g_zn4);
    __half* yx    = (__half*)sym_addr(g_yx);
    __half* h16   = (__half*)sym_addr(g_h16);

    // 1) fused init: zero counts/stats + y->fp16
    init_k<<<cdiv_u((long long)E * 2, 256), 256>>>(y, y16, E, N);

    // 2) CSR build for both graphs (fused dual launches)
    hist_dual<<<cdiv_u((long long)EL + E, 256), 256>>>(dst_lg, dst_g, EL, E);

    int nb_lg = cdiv_u(E, 1024);
    int nb_g  = cdiv_u(N, 1024);
    scan_blocks_dual<<<nb_lg + nb_g, 256>>>(nb_lg, E, N);
    scan_bsums_dual<<<2, 1024>>>(nb_lg, nb_g);
    add_offsets_dual<<<cdiv_u((long long)E + N, 256), 256>>>(E, N, EL);
    scatter_dual<<<cdiv_u((long long)EL + E, 256), 256>>>(src_lg, dst_lg, src_g, dst_g, EL, E);

    // 3) fused chains: pass k runs lg + g concurrently in one launch
    unsigned gall = cdiv_u((long long)(E + N) * 4, 256);
    pass1_dual<<<gall, 256>>>(y16, x, eid2nid, ze1, xyagg, E, zn1, yx, N);
    spmm_dual<<<gall, 256>>>(ze1, ze2, E, zn1, zn2, N);
    spmm_dual<<<gall, 256>>>(ze2, zet, E, zn2, znt, N);
    spmm_dual<<<gall, 256>>>(zet, ze4, E, znt, zn4, N);

    // 4) fused GEMM (node + edge in one launch) -> fp16 h
    int gridN = cdiv_u(N, 512);
    int gridE = cdiv_u(E, 512);
    gemm_dual<<<gridN + gridE, 256>>>(x, y16, deg_g, deg_lg,
                                      yx, zn1, zn2, zn4,
                                      xyagg, ze1, ze2, ze4,
                                      theta_W, theta_b, gamma_W, gamma_b,
                                      h16, N, E, gridN);

    // 5) BN finalize + apply (fp16 h in -> fp32 d_out)
    bn_finalize<<<1, 32>>>(bn_x_w, bn_x_b, bn_y_w, bn_y_b, N, E);
    bn_apply_all<<<cdiv_u((long long)(N + E) * 4, 256), 256>>>(h16, out_all, N, E);

    (void)n_in; (void)out_size;
}

// round 17
// speedup vs baseline: 1.0961x; 1.0443x over previous
#include <cuda_runtime.h>
#include <cuda_fp16.h>
#include <cstdint>

#define N_MAX   100000
#define E_MAX   1600000
#define EL_MAX  6400000

// ---------------- scratch (device globals; fp16 chain intermediates) ----------
__device__ __half g_y16[E_MAX * 16];
__device__ __half g_ze1[E_MAX * 16];
__device__ __half g_ze2[E_MAX * 16];
__device__ __half g_zet[E_MAX * 16];
__device__ __half g_ze4[E_MAX * 16];
__device__ __half g_xyagg[E_MAX * 16];
__device__ __half g_zn1[N_MAX * 16];
__device__ __half g_zn2[N_MAX * 16];
__device__ __half g_znt[N_MAX * 16];
__device__ __half g_zn4[N_MAX * 16];
__device__ __half g_yx[N_MAX * 16];
__device__ __half g_h16[(N_MAX + E_MAX) * 16];   // pre-BN activations, fp16

__device__ int g_tmp_lg[E_MAX];        // counts, then cursors
__device__ int g_off_lg[E_MAX + 1];
__device__ int g_csr_lg[EL_MAX];
__device__ int g_tmp_g[N_MAX];
__device__ int g_off_g[N_MAX + 1];
__device__ int g_csr_g_src[E_MAX];
__device__ int g_csr_g_eid[E_MAX];
__device__ int g_bsums_lg[2048];
__device__ int g_bsums_g[256];

__device__ float g_stats[64];
__device__ float g_bn[64];

static inline unsigned cdiv_u(long long a, long long b) { return (unsigned)((a + b - 1) / b); }

// ---------------- f32x2 helpers ----------------
__device__ __forceinline__ unsigned long long pk2(float a, float b) {
    unsigned long long r;
    asm("mov.b64 %0, {%1, %2};" : "=l"(r) : "r"(__float_as_uint(a)), "r"(__float_as_uint(b)));
    return r;
}
__device__ __forceinline__ unsigned long long fma2(
    unsigned long long a, unsigned long long b, unsigned long long c) {
    unsigned long long d;
    asm("fma.rn.f32x2 %0, %1, %2, %3;" : "=l"(d) : "l"(a), "l"(b), "l"(c));
    return d;
}
__device__ __forceinline__ void up2(unsigned long long v, float& lo, float& hi) {
    unsigned int a, b;
    asm("mov.b64 {%0, %1}, %2;" : "=r"(a), "=r"(b) : "l"(v));
    lo = __uint_as_float(a); hi = __uint_as_float(b);
}

// ---------------- fp16 pack/unpack helpers ----------------
__device__ __forceinline__ uint2 f4_to_h8(float4 a) {
    uint2 o;
    __half2 lo = __floats2half2_rn(a.x, a.y);
    __half2 hi = __floats2half2_rn(a.z, a.w);
    o.x = *reinterpret_cast<unsigned*>(&lo);
    o.y = *reinterpret_cast<unsigned*>(&hi);
    return o;
}
__device__ __forceinline__ float4 h8_to_f4(uint2 raw) {
    float2 f0 = __half22float2(*reinterpret_cast<__half2*>(&raw.x));
    float2 f1 = __half22float2(*reinterpret_cast<__half2*>(&raw.y));
    return make_float4(f0.x, f0.y, f1.x, f1.y);
}
__device__ __forceinline__ void h16_to_f(uint4 ra, uint4 rb, float* v) {
    __half2* h = reinterpret_cast<__half2*>(&ra);
    #pragma unroll
    for (int i = 0; i < 4; i++) {
        float2 f = __half22float2(h[i]);
        v[2 * i] = f.x; v[2 * i + 1] = f.y;
    }
    __half2* h2 = reinterpret_cast<__half2*>(&rb);
    #pragma unroll
    for (int i = 0; i < 4; i++) {
        float2 f = __half22float2(h2[i]);
        v[8 + 2 * i] = f.x; v[8 + 2 * i + 1] = f.y;
    }
}
__device__ __forceinline__ uint4 f8_to_h8(const float* v) {
    uint4 o;
    __half2 a = __floats2half2_rn(v[0], v[1]);
    __half2 b = __floats2half2_rn(v[2], v[3]);
    __half2 c = __floats2half2_rn(v[4], v[5]);
    __half2 d = __floats2half2_rn(v[6], v[7]);
    o.x = *reinterpret_cast<unsigned*>(&a);
    o.y = *reinterpret_cast<unsigned*>(&b);
    o.z = *reinterpret_cast<unsigned*>(&c);
    o.w = *reinterpret_cast<unsigned*>(&d);
    return o;
}

// ---------------- init: zero counts/stats + y->fp16 conversion (fused) --------
__global__ void __launch_bounds__(256) init_k(
    const float* __restrict__ y, __half* __restrict__ y16, int nE, int nN)
{
    long long i = (long long)blockIdx.x * 256 + threadIdx.x;
    long long n8 = (long long)nE * 2;   // 8-elem chunks of y
    if (i < n8) {
        const float4* p = (const float4*)y + i * 2;
        float4 a = __ldg(p), b = __ldg(p + 1);
        uint2 ra = f4_to_h8(a), rb = f4_to_h8(b);
        ((uint4*)y16)[i] = make_uint4(ra.x, ra.y, rb.x, rb.y);
    }
    if (i < nE) g_tmp_lg[i] = 0;
    if (i < nN) g_tmp_g[i] = 0;
    if (i < 64) g_stats[i] = 0.f;
}

// ---------------- CSR build (dual-graph fused launches) ----------------
__global__ void __launch_bounds__(256) hist_dual(
    const int* __restrict__ dst_lg, const int* __restrict__ dst_g, int nEL, int nE)
{
    long long i = (long long)blockIdx.x * 256 + threadIdx.x;
    if (i < nEL) {
        atomicAdd(g_tmp_lg + __ldg(dst_lg + i), 1);
    } else {
        long long j = i - nEL;
        if (j < nE) atomicAdd(g_tmp_g + __ldg(dst_g + j), 1);
    }
}

__device__ __forceinline__ void scan_block_body(
    const int* cnt, int* off, int* bsums, int n, int blk)
{
    __shared__ int warpsum[8];
    int t = threadIdx.x;
    int i0 = blk * 1024 + t * 4;
    int4 v = make_int4(0, 0, 0, 0);
    if (i0 + 3 < n) v = *(const int4*)(cnt + i0);
    else {
        if (i0 < n)     v.x = cnt[i0];
        if (i0 + 1 < n) v.y = cnt[i0 + 1];
        if (i0 + 2 < n) v.z = cnt[i0 + 2];
    }
    int s = v.x + v.y + v.z + v.w;
    int lane = t & 31, w = t >> 5;
    int incl = s;
    #pragma unroll
    for (int o = 1; o < 32; o <<= 1) {
        int nv = __shfl_up_sync(0xFFFFFFFFu, incl, o);
        if (lane >= o) incl += nv;
    }
    if (lane == 31) warpsum[w] = incl;
    __syncthreads();
    if (t < 8) {
        int ws = warpsum[t];
        int in2 = ws;
        #pragma unroll
        for (int o = 1; o < 8; o <<= 1) {
            int nv = __shfl_up_sync(0x000000FFu, in2, o);
            if (t >= o) in2 += nv;
        }
        warpsum[t] = in2 - ws;  // exclusive
    }
    __syncthreads();
    int excl = warpsum[w] + incl - s;
    if (i0 < n) {
        int a = excl;
        off[i0] = a; a += v.x;
        if (i0 + 1 < n) off[i0 + 1] = a; a += v.y;
        if (i0 + 2 < n) off[i0 + 2] = a; a += v.z;
        if (i0 + 3 < n) off[i0 + 3] = a;
    }
    if (t == 255) bsums[blk] = excl + s;  // block total
}

__global__ void __launch_bounds__(256) scan_blocks_dual(int nb_lg, int nE, int nN) {
    int b = blockIdx.x;
    if (b < nb_lg) scan_block_body(g_tmp_lg, g_off_lg, g_bsums_lg, nE, b);
    else           scan_block_body(g_tmp_g,  g_off_g,  g_bsums_g,  nN, b - nb_lg);
}

__device__ __forceinline__ void scan_bsums_body(int* bsums, int nb) {
    __shared__ int wsum[32];
    int t = threadIdx.x;
    int k = (nb + 1023) >> 10;
    int i0 = t * k;
    int s = 0;
    for (int q = 0; q < k; q++) { int i = i0 + q; if (i < nb) s += bsums[i]; }
    int lane = t & 31, w = t >> 5;
    int incl = s;
    #pragma unroll
    for (int o = 1; o < 32; o <<= 1) {
        int nv = __shfl_up_sync(0xFFFFFFFFu, incl, o);
        if (lane >= o) incl += nv;
    }
    if (lane == 31) wsum[w] = incl;
    __syncthreads();
    if (t < 32) {
        int ws = wsum[t];
        int in2 = ws;
        #pragma unroll
        for (int o = 1; o < 32; o <<= 1) {
            int nv = __shfl_up_sync(0xFFFFFFFFu, in2, o);
            if (t >= o) in2 += nv;
        }
        wsum[t] = in2 - ws;
    }
    __syncthreads();
    int excl = wsum[w] + incl - s;
    for (int q = 0; q < k; q++) {
        int i = i0 + q;
        if (i < nb) { int v = bsums[i]; bsums[i] = excl; excl += v; }
    }
}

__global__ void __launch_bounds__(1024) scan_bsums_dual(int nb_lg, int nb_g) {
    if (blockIdx.x == 0) scan_bsums_body(g_bsums_lg, nb_lg);
    else                 scan_bsums_body(g_bsums_g,  nb_g);
}

__global__ void __launch_bounds__(256) add_offsets_dual(int nE, int nN, int nEL) {
    long long i = (long long)blockIdx.x * 256 + threadIdx.x;
    if (i < nE) {
        int v = g_off_lg[i] + __ldg(g_bsums_lg + (i >> 10));
        g_off_lg[i] = v;
        g_tmp_lg[i] = v;
        if (i == 0) g_off_lg[nE] = nEL;
    } else {
        long long j = i - nE;
        if (j < nN) {
            int v = g_off_g[j] + __ldg(g_bsums_g + (j >> 10));
            g_off_g[j] = v;
            g_tmp_g[j] = v;
            if (j == 0) g_off_g[nN] = nE;
        }
    }
}

__global__ void __launch_bounds__(256) scatter_dual(
    const int* __restrict__ src_lg, const int* __restrict__ dst_lg,
    const int* __restrict__ src_g, const int* __restrict__ dst_g,
    int nEL, int nE)
{
    long long i = (long long)blockIdx.x * 256 + threadIdx.x;
    if (i < nEL) {
        int p = atomicAdd(g_tmp_lg + __ldg(dst_lg + i), 1);
        g_csr_lg[p] = __ldg(src_lg + i);
    } else {
        long long j = i - nEL;
        if (j < nE) {
            int p = atomicAdd(g_tmp_g + __ldg(dst_g + j), 1);
            g_csr_g_src[p] = __ldg(src_g + j);
            g_csr_g_eid[p] = (int)j;
        }
    }
}

// ---------------- chain pass (lg + g fused), 2 lanes/row (16B loads) ----------
// Doubles rows-in-flight vs 4 lanes/row: resident threads are capped, so fewer
// threads per row = more distinct outstanding sectors = better latency hiding.
__global__ void __launch_bounds__(256) spmm_dual2(
    const __half* __restrict__ z_lg, __half* __restrict__ out_lg, int nlg,
    const __half* __restrict__ z_g,  __half* __restrict__ out_g,  int ng)
{
    long long t = (long long)blockIdx.x * 256 + threadIdx.x;
    long long lgT = (long long)nlg * 2;
    const __half* z;
    __half* outp;
    int d, c;
    const int* offp;
    const int* csrp;
    if (t < lgT) {
        d = (int)(t >> 1); c = (int)(t & 1);
        z = z_lg; outp = out_lg; offp = g_off_lg; csrp = g_csr_lg;
    } else {
        long long u = t - lgT;
        if (u >= (long long)ng * 2) return;
        d = (int)(u >> 1); c = (int)(u & 1);
        z = z_g; outp = out_g; offp = g_off_g; csrp = g_csr_g_src;
    }
    int k0 = __ldg(offp + d), k1 = __ldg(offp + d + 1);
    float acc[8];
    #pragma unroll
    for (int q = 0; q < 8; q++) acc[q] = 0.f;
    #pragma unroll 4
    for (int k = k0; k < k1; k++) {
        int s = __ldg(csrp + k);
        uint4 raw = __ldg((const uint4*)z + (size_t)s * 2 + c);
        const __half2* h = reinterpret_cast<const __half2*>(&raw);
        #pragma unroll
        for (int q = 0; q < 4; q++) {
            float2 f = __half22float2(h[q]);
            acc[2 * q] += f.x; acc[2 * q + 1] += f.y;
        }
    }
    ((uint4*)outp)[(size_t)d * 2 + c] = f8_to_h8(acc);
}

// pass1 fused: lg: ze1 = A y16, xyagg = A x[e2n];  g: zn1 = A x, yx = sum y16[eid]
__global__ void __launch_bounds__(256) pass1_dual(
    const __half* __restrict__ y16, const float* __restrict__ x,
    const int* __restrict__ e2n,
    __half* __restrict__ ze1, __half* __restrict__ xyagg, int nlg,
    __half* __restrict__ zn1, __half* __restrict__ yx, int ng)
{
    long long t = (long long)blockIdx.x * 256 + threadIdx.x;
    long long lgT = (long long)nlg * 4;
    if (t < lgT) {
        int d = (int)(t >> 2), c = (int)(t & 3);
        int k0 = __ldg(g_off_lg + d), k1 = __ldg(g_off_lg + d + 1);
        float4 ay = make_float4(0.f, 0.f, 0.f, 0.f);
        float4 ax = make_float4(0.f, 0.f, 0.f, 0.f);
        #pragma unroll 4
        for (int k = k0; k < k1; k++) {
            int s = __ldg(g_csr_lg + k);
            float4 v = h8_to_f4(__ldg((const uint2*)y16 + (size_t)s * 4 + c));
            ay.x += v.x; ay.y += v.y; ay.z += v.z; ay.w += v.w;
            int nid = __ldg(e2n + s);
            float4 w = __ldg((const float4*)x + (size_t)nid * 4 + c);
            ax.x += w.x; ax.y += w.y; ax.z += w.z; ax.w += w.w;
        }
        ((uint2*)ze1)[(size_t)d * 4 + c] = f4_to_h8(ay);
        ((uint2*)xyagg)[(size_t)d * 4 + c] = f4_to_h8(ax);
    } else {
        long long u = t - lgT;
        if (u >= (long long)ng * 4) return;
        int d = (int)(u >> 2), c = (int)(u & 3);
        int k0 = __ldg(g_off_g + d), k1 = __ldg(g_off_g + d + 1);
        float4 ax = make_float4(0.f, 0.f, 0.f, 0.f);
        float4 ay = make_float4(0.f, 0.f, 0.f, 0.f);
        #pragma unroll 4
        for (int k = k0; k < k1; k++) {
            int s = __ldg(g_csr_g_src + k);
            int e = __ldg(g_csr_g_eid + k);
            float4 v = __ldg((const float4*)x + (size_t)s * 4 + c);
            ax.x += v.x; ax.y += v.y; ax.z += v.z; ax.w += v.w;
            float4 w = h8_to_f4(__ldg((const uint2*)y16 + (size_t)e * 4 + c));
            ay.x += w.x; ay.y += w.y; ay.z += w.z; ay.w += w.w;
        }
        ((uint2*)zn1)[(size_t)d * 4 + c] = f4_to_h8(ax);
        ((uint2*)yx)[(size_t)d * 4 + c] = f4_to_h8(ay);
    }
}

// ---------------- fused 6-way lin + relu-fold + BN stats (both branches) ------
__global__ void __launch_bounds__(256) gemm_dual(
    const float* __restrict__ x, const __half* __restrict__ y16,
    const float* __restrict__ deg_g, const float* __restrict__ deg_lg,
    const __half* __restrict__ yx, const __half* __restrict__ zn1,
    const __half* __restrict__ zn2, const __half* __restrict__ zn4,
    const __half* __restrict__ xyagg, const __half* __restrict__ ze1,
    const __half* __restrict__ ze2, const __half* __restrict__ ze4,
    const float* __restrict__ theta_W, const float* __restrict__ theta_b,
    const float* __restrict__ gamma_W, const float* __restrict__ gamma_b,
    __half* __restrict__ h16, int N, int E, int gridN)
{
    __shared__ float ws[96 * 32];
    __shared__ unsigned long long bs2[16];
    __shared__ float redbuf[8 * 32];

    int statsel = (blockIdx.x < gridN) ? 0 : 1;
    int blk = statsel ? (blockIdx.x - gridN) : blockIdx.x;
    int nrows = statsel ? E : N;
    const float*  in0f = statsel ? nullptr : x;
    const __half* in0h = statsel ? y16 : nullptr;
    const float*  deg  = statsel ? deg_lg : deg_g;
    const __half* agg  = statsel ? xyagg : yx;
    const __half* z1p  = statsel ? ze1 : zn1;
    const __half* z2p  = statsel ? ze2 : zn2;
    const __half* z4p  = statsel ? ze4 : zn4;
    const float*  W    = statsel ? gamma_W : theta_W;
    const float*  Bv   = statsel ? gamma_b : theta_b;
    __half* hout = statsel ? (h16 + (size_t)N * 16) : h16;

    for (int t = threadIdx.x; t < 96 * 32; t += 256) {
        int kb = t >> 9;
        int rem = t & 511;
        int j = rem >> 4;
        int i = rem & 15;
        ws[(kb * 16 + i) * 32 + j] = W[t];
    }
    if (threadIdx.x < 16) {
        float lo = 0.f, hi = 0.f;
        #pragma unroll
        for (int kb = 0; kb < 6; kb++) {
            lo += Bv[kb * 32 + 2 * threadIdx.x];
            hi += Bv[kb * 32 + 2 * threadIdx.x + 1];
        }
        bs2[threadIdx.x] = pk2(lo, hi);
    }
    __syncthreads();

    int r0 = blk * 512 + threadIdx.x;
    int r1 = r0 + 256;
    bool ok0 = r0 < nrows, ok1 = r1 < nrows;

    unsigned long long acc0[16], acc1[16];
    #pragma unroll
    for (int q = 0; q < 16; q++) { acc0[q] = bs2[q]; acc1[q] = bs2[q]; }

    float v0[16], v1[16];
    #pragma unroll
    for (int q = 0; q < 16; q++) { v0[q] = 0.f; v1[q] = 0.f; }
    float dg0 = ok0 ? __ldg(deg + r0) : 0.f;
    float dg1 = ok1 ? __ldg(deg + r1) : 0.f;

    #pragma unroll 1
    for (int kb = 0; kb < 6; kb++) {
        if (kb <= 1) {
            if (kb == 0) {
                if (in0h) {
                    if (ok0) {
                        const uint4* hp = (const uint4*)in0h + (size_t)r0 * 2;
                        uint4 ra = __ldg(hp), rb = __ldg(hp + 1);
                        h16_to_f(ra, rb, v0);
                    }
                    if (ok1) {
                        const uint4* hp = (const uint4*)in0h + (size_t)r1 * 2;
                        uint4 ra = __ldg(hp), rb = __ldg(hp + 1);
                        h16_to_f(ra, rb, v1);
                    }
                } else {
                    if (ok0) {
                        const float4* p = (const float4*)in0f + (size_t)r0 * 4;
                        float4 a = __ldg(p), b = __ldg(p + 1), c = __ldg(p + 2), d = __ldg(p + 3);
                        v0[0]=a.x; v0[1]=a.y; v0[2]=a.z; v0[3]=a.w;
                        v0[4]=b.x; v0[5]=b.y; v0[6]=b.z; v0[7]=b.w;
                        v0[8]=c.x; v0[9]=c.y; v0[10]=c.z; v0[11]=c.w;
                        v0[12]=d.x; v0[13]=d.y; v0[14]=d.z; v0[15]=d.w;
                    }
                    if (ok1) {
                        const float4* p = (const float4*)in0f + (size_t)r1 * 4;
                        float4 a = __ldg(p), b = __ldg(p + 1), c = __ldg(p + 2), d = __ldg(p + 3);
                        v1[0]=a.x; v1[1]=a.y; v1[2]=a.z; v1[3]=a.w;
                        v1[4]=b.x; v1[5]=b.y; v1[6]=b.z; v1[7]=b.w;
                        v1[8]=c.x; v1[9]=c.y; v1[10]=c.z; v1[11]=c.w;
                        v1[12]=d.x; v1[13]=d.y; v1[14]=d.z; v1[15]=d.w;
                    }
                }
            } else {
                #pragma unroll
                for (int q = 0; q < 16; q++) { v0[q] *= dg0; v1[q] *= dg1; }
            }
        } else {
            const __half* sp = (kb == 2) ? agg : (kb == 3) ? z1p
                             : (kb == 4) ? z2p : z4p;
            if (ok0) {
                const uint4* hp = (const uint4*)sp + (size_t)r0 * 2;
                uint4 ra = __ldg(hp), rb = __ldg(hp + 1);
                h16_to_f(ra, rb, v0);
            }
            if (ok1) {
                const uint4* hp = (const uint4*)sp + (size_t)r1 * 2;
                uint4 ra = __ldg(hp), rb = __ldg(hp + 1);
                h16_to_f(ra, rb, v1);
            }
        }
        #pragma unroll
        for (int i = 0; i < 16; i++) {
            unsigned long long vd0 = pk2(v0[i], v0[i]);
            unsigned long long vd1 = pk2(v1[i], v1[i]);
            const ulonglong2* wp2 = (const ulonglong2*)&ws[(kb * 16 + i) * 32];
            #pragma unroll
            for (int q2 = 0; q2 < 8; q2++) {
                ulonglong2 ww = wp2[q2];
                acc0[2*q2]   = fma2(vd0, ww.x, acc0[2*q2]);
                acc0[2*q2+1] = fma2(vd0, ww.y, acc0[2*q2+1]);
                acc1[2*q2]   = fma2(vd1, ww.x, acc1[2*q2]);
                acc1[2*q2+1] = fma2(vd1, ww.y, acc1[2*q2+1]);
            }
        }
    }

    float hs[16], hq[16];
    #pragma unroll
    for (int c = 0; c < 16; c++) { hs[c] = 0.f; hq[c] = 0.f; }

    if (ok0) {
        float h[16];
        #pragma unroll
        for (int q = 0; q < 8; q++) {
            float a0, a1, b0, b1;
            up2(acc0[q], a0, a1);
            up2(acc0[8 + q], b0, b1);
            h[2*q]   = a0 + fmaxf(b0, 0.f);
            h[2*q+1] = a1 + fmaxf(b1, 0.f);
        }
        uint4* ho = (uint4*)hout + (size_t)r0 * 2;
        ho[0] = f8_to_h8(h);
        ho[1] = f8_to_h8(h + 8);
        #pragma unroll
        for (int c = 0; c < 16; c++) { hs[c] += h[c]; hq[c] += h[c] * h[c]; }
    }
    if (ok1) {
        float h[16];
        #pragma unroll
        for (int q = 0; q < 8; q++) {
            float a0, a1, b0, b1;
            up2(acc1[q], a0, a1);
            up2(acc1[8 + q], b0, b1);
            h[2*q]   = a0 + fmaxf(b0, 0.f);
            h[2*q+1] = a1 + fmaxf(b1, 0.f);
        }
        uint4* ho = (uint4*)hout + (size_t)r1 * 2;
        ho[0] = f8_to_h8(h);
        ho[1] = f8_to_h8(h + 8);
        #pragma unroll
        for (int c = 0; c < 16; c++) { hs[c] += h[c]; hq[c] += h[c] * h[c]; }
    }

    int lane = threadIdx.x & 31;
    int warp = threadIdx.x >> 5;
    #pragma unroll
    for (int c = 0; c < 16; c++) {
        float a = hs[c];
        float b = hq[c];
        #pragma unroll
        for (int o = 16; o > 0; o >>= 1) {
            a += __shfl_xor_sync(0xFFFFFFFFu, a, o);
            b += __shfl_xor_sync(0xFFFFFFFFu, b, o);
        }
        if (lane == 0) {
            redbuf[warp * 32 + c]      = a;
            redbuf[warp * 32 + 16 + c] = b;
        }
    }
    __syncthreads();
    if (threadIdx.x < 32) {
        float s = 0.f;
        #pragma unroll
        for (int w = 0; w < 8; w++) s += redbuf[w * 32 + threadIdx.x];
        atomicAdd(&g_stats[statsel * 32 + threadIdx.x], s);
    }
}

// ---------------- BN finalize + apply (reads fp16 h, writes fp32 output) -------
__global__ void bn_finalize(
    const float* __restrict__ wx, const float* __restrict__ bx,
    const float* __restrict__ wy, const float* __restrict__ by,
    int N, int E)
{
    int t = threadIdx.x;
    if (t >= 32) return;
    int sel = t >> 4;
    int c = t & 15;
    float cnt = sel ? (float)E : (float)N;
    float m   = g_stats[sel * 32 + c] / cnt;
    float var = g_stats[sel * 32 + 16 + c] / cnt - m * m;
    const float* w = sel ? wy : wx;
    const float* b = sel ? by : bx;
    float scale = rsqrtf(var + 1e-5f) * __ldg(w + c);
    g_bn[sel * 32 + c]      = scale;
    g_bn[sel * 32 + 16 + c] = __ldg(b + c) - m * scale;
}

__global__ void __launch_bounds__(256) bn_apply_all(
    const __half* __restrict__ h16, float* __restrict__ outp, int N, int E)
{
    long long i = (long long)blockIdx.x * blockDim.x + threadIdx.x;  // quarter-row index
    long long nx = (long long)N * 4;
    long long tot = nx + (long long)E * 4;
    if (i >= tot) return;
    int bnoff = (i < nx) ? 0 : 32;
    int c = ((int)(i & 3)) * 4;
    const float* bn = g_bn + bnoff;
    float4 v = h8_to_f4(__ldg((const uint2*)h16 + i));
    v.x = v.x * bn[c + 0] + bn[16 + c + 0];
    v.y = v.y * bn[c + 1] + bn[16 + c + 1];
    v.z = v.z * bn[c + 2] + bn[16 + c + 2];
    v.w = v.w * bn[c + 3] + bn[16 + c + 3];
    __stcs((float4*)outp + i, v);   // output never re-read: streaming store
}

// ---------------- host ----------------
static void* sym_addr(const void* s) {
    void* p = nullptr;
    cudaGetSymbolAddress(&p, s);
    return p;
}

extern "C" void kernel_launch(void* const* d_in, const int* in_sizes, int n_in,
                              void* d_out, int out_size)
{
    const float* x       = (const float*)d_in[0];
    const float* y       = (const float*)d_in[1];
    const float* deg_g   = (const float*)d_in[2];
    const float* deg_lg  = (const float*)d_in[3];
    const float* theta_W = (const float*)d_in[4];
    const float* theta_b = (const float*)d_in[5];
    const float* gamma_W = (const float*)d_in[6];
    const float* gamma_b = (const float*)d_in[7];
    const float* bn_x_w  = (const float*)d_in[8];
    const float* bn_x_b  = (const float*)d_in[9];
    const float* bn_y_w  = (const float*)d_in[10];
    const float* bn_y_b  = (const float*)d_in[11];
    const int* src_g     = (const int*)d_in[12];
    const int* dst_g     = (const int*)d_in[13];
    const int* src_lg    = (const int*)d_in[14];
    const int* dst_lg    = (const int*)d_in[15];
    const int* eid2nid   = (const int*)d_in[16];

    int N  = in_sizes[0] / 16;
    int E  = in_sizes[1] / 16;
    int EL = in_sizes[14];

    float* out_all = (float*)d_out;

    __half* y16   = (__half*)sym_addr(g_y16);
    __half* ze1   = (__half*)sym_addr(g_ze1);
    __half* ze2   = (__half*)sym_addr(g_ze2);
    __half* zet   = (__half*)sym_addr(g_zet);
    __half* ze4   = (__half*)sym_addr(g_ze4);
    __half* xyagg = (__half*)sym_addr(g_xyagg);
    __half* zn1   = (__half*)sym_addr(g_zn1);
    __half* zn2   = (__half*)sym_addr(g_zn2);
    __half* znt   = (__half*)sym_addr(g_znt);
    __half* zn4   = (__half*)sym_addr(g_zn4);
    __half* yx    = (__half*)sym_addr(g_yx);
    __half* h16   = (__half*)sym_addr(g_h16);

    // 1) fused init: zero counts/stats + y->fp16
    init_k<<<cdiv_u((long long)E * 2, 256), 256>>>(y, y16, E, N);

    // 2) CSR build for both graphs (fused dual launches)
    hist_dual<<<cdiv_u((long long)EL + E, 256), 256>>>(dst_lg, dst_g, EL, E);

    int nb_lg = cdiv_u(E, 1024);
    int nb_g  = cdiv_u(N, 1024);
    scan_blocks_dual<<<nb_lg + nb_g, 256>>>(nb_lg, E, N);
    scan_bsums_dual<<<2, 1024>>>(nb_lg, nb_g);
    add_offsets_dual<<<cdiv_u((long long)E + N, 256), 256>>>(E, N, EL);
    scatter_dual<<<cdiv_u((long long)EL + E, 256), 256>>>(src_lg, dst_lg, src_g, dst_g, EL, E);

    // 3) fused chains: pass1 (4 lanes/row), then chained passes (2 lanes/row)
    unsigned gall4 = cdiv_u((long long)(E + N) * 4, 256);
    unsigned gall2 = cdiv_u((long long)(E + N) * 2, 256);
    pass1_dual<<<gall4, 256>>>(y16, x, eid2nid, ze1, xyagg, E, zn1, yx, N);
    spmm_dual2<<<gall2, 256>>>(ze1, ze2, E, zn1, zn2, N);
    spmm_dual2<<<gall2, 256>>>(ze2, zet, E, zn2, znt, N);
    spmm_dual2<<<gall2, 256>>>(zet, ze4, E, znt, zn4, N);

    // 4) fused GEMM (node + edge in one launch) -> fp16 h
    int gridN = cdiv_u(N, 512);
    int gridE = cdiv_u(E, 512);
    gemm_dual<<<gridN + gridE, 256>>>(x, y16, deg_g, deg_lg,
                                      yx, zn1, zn2, zn4,
                                      xyagg, ze1, ze2, ze4,
                                      theta_W, theta_b, gamma_W, gamma_b,
                                      h16, N, E, gridN);

    // 5) BN finalize + apply (fp16 h in -> fp32 d_out)
    bn_finalize<<<1, 32>>>(bn_x_w, bn_x_b, bn_y_w, bn_y_b, N, E);
    bn_apply_all<<<cdiv_u((long long)(N + E) * 4, 256), 256>>>(h16, out_all, N, E);

    (void)n_in; (void)out_size;
}